// round 16
// baseline (speedup 1.0000x reference)
#include <cuda_runtime.h>
#include <cstdint>

#define NN 8192
#define KB 4096               // histogram buckets (fine sort -> tight bounds)
#define NCHUNK 256            // 256 chunks of 32 sorted candidates
#define GA 64                 // kernel A grid (128 thr: 64*128 = 8192)
#define SCTA 32               // scatter CTAs inside kernel B (256 thr each)

// Scratch (device globals — no allocation allowed in kernel_launch).
// Zero-initialized at load; counters/hist are self-resetting per replay.
__device__ float    g_s[NN];          // s[j] by original index
__device__ float    g_wm[NN];         // wmax[j] by original index
__device__ int      g_bk[NN];         // bucket id by original index
__device__ __align__(16) int g_hist[KB];
__device__ __align__(16) int g_cur[KB];
__device__ float    g_ss[NN];         // s in bucket-sorted order
__device__ float    g_ws[NN];         // wmax in bucket-sorted order
__device__ int      g_idx[NN];        // original index in bucket-sorted order
__device__ unsigned g_csmin[NCHUNK];  // per-chunk min s (float bits, atomicMin)
__device__ unsigned g_cwmax[NCHUNK];  // per-chunk max w (float bits, atomicMax)
__device__ unsigned g_cnsmin[NCHUNK]; // per-chunk max -s*w (neg float bits, atomicMin)
__device__ float    g_bmin[NCHUNK];   // FINAL suffix min s
__device__ float    g_bwub[NCHUNK];   // FINAL suffix max w
__device__ float    g_bnsw[NCHUNK];   // FINAL suffix max -s*w
__device__ int      g_doneA;
__device__ int      g_doneB;
__device__ int      g_flag;

// ---------------------------------------------------------------------------
// Kernel A: bucket + (last CTA) scan + init + counter resets — one launch.
// ---------------------------------------------------------------------------
__global__ __launch_bounds__(128)
void prep_kernel(const float* __restrict__ x, const float* __restrict__ Wphi) {
    const int t = threadIdx.x;
    const int j = blockIdx.x * 128 + t;

    float s = x[3 * j + 0] + x[3 * j + 1] + x[3 * j + 2];
    float w0 = Wphi[j], w1 = Wphi[NN + j], w2 = Wphi[2 * NN + j];
    float w = fmaxf(w0, fmaxf(w1, w2));
    int b = (int)(s * (KB / 3.0f));
    b = max(0, min(KB - 1, b));
    g_s[j]  = s;
    g_wm[j] = w;
    g_bk[j] = b;
    atomicAdd(&g_hist[b], 1);

    // isLastBlockDone: release own writes, then count
    __shared__ int isLast;
    __threadfence();
    __syncthreads();
    if (t == 0) isLast = (atomicAdd(&g_doneA, 1) == GA - 1);
    __syncthreads();
    if (!isLast) return;

    // ---- Last CTA: exclusive scan of g_hist[4096] -> g_cur (128 threads,
    //      32 contiguous buckets each), zero hist, init stats, reset counters.
    const int lane = t & 31, wid = t >> 5;
    __shared__ int warpsums[4];

    int4 h[8];
    int lsum = 0;
    #pragma unroll
    for (int q = 0; q < 8; q++) {
        h[q] = reinterpret_cast<const int4*>(g_hist)[t * 8 + q];
        lsum += h[q].x + h[q].y + h[q].z + h[q].w;
        reinterpret_cast<int4*>(g_hist)[t * 8 + q] = make_int4(0, 0, 0, 0);
    }
    int inc = lsum;
    #pragma unroll
    for (int off = 1; off < 32; off <<= 1) {
        int n = __shfl_up_sync(0xffffffffu, inc, off);
        if (lane >= off) inc += n;
    }
    if (lane == 31) warpsums[wid] = inc;
    __syncthreads();
    if (t == 0) {
        int acc = 0;
        #pragma unroll
        for (int q = 0; q < 4; q++) { int v = warpsums[q]; warpsums[q] = acc; acc += v; }
    }
    __syncthreads();
    int run = warpsums[wid] + (inc - lsum);
    #pragma unroll
    for (int q = 0; q < 8; q++) {
        int4 o;
        o.x = run;  run += h[q].x;
        o.y = run;  run += h[q].y;
        o.z = run;  run += h[q].z;
        o.w = run;  run += h[q].w;
        reinterpret_cast<int4*>(g_cur)[t * 8 + q] = o;
    }
    #pragma unroll
    for (int q = 0; q < 2; q++) {
        int c = t + q * 128;
        g_csmin[c]  = 0x7F800000u;   // +inf
        g_cwmax[c]  = 0u;            // 0.0f (all w > 0)
        g_cnsmin[c] = 0xFFFFFFFFu;   // most-negative float bits
    }
    if (t == 0) { g_doneA = 0; g_doneB = 0; g_flag = 0; }
}

// ---------------------------------------------------------------------------
// Kernel B: CTAs 0..31 scatter; last scatter CTA computes suffix bounds and
// releases g_flag; everyone then probes 8 rows (warp per row, R8 loop).
// ---------------------------------------------------------------------------
__global__ __launch_bounds__(256)
void probe_kernel(const int* __restrict__ adj, float* __restrict__ out) {
    __shared__ float s_cmin[NCHUNK], s_cwub[NCHUNK], s_cnsw[NCHUNK];

    const int t = threadIdx.x;
    const int lane = t & 31;
    const int warp = t >> 5;
    const int bid = blockIdx.x;

    if (bid < SCTA) {
        // --- Scatter: 256 elements per CTA; fold chunk stats via bit atomics
        // (s>0, w>0 -> int bits monotone; -s*w<=0 -> uint-min == float-max).
        const int j = bid * 256 + t;
        float s = g_s[j];
        float w = g_wm[j];
        int pos = atomicAdd(&g_cur[g_bk[j]], 1);
        g_ss[pos]  = s;
        g_ws[pos]  = w;
        g_idx[pos] = j;
        int c = pos >> 5;
        atomicMin(&g_csmin[c],  __float_as_uint(s));
        atomicMax(&g_cwmax[c],  __float_as_uint(w));
        atomicMin(&g_cnsmin[c], __float_as_uint(-s * w));

        __shared__ int isLast;
        __threadfence();
        __syncthreads();
        if (t == 0) isLast = (atomicAdd(&g_doneB, 1) == SCTA - 1);
        __syncthreads();
        if (isLast && warp == 0) {
            // Single-warp suffix scan over 256 chunks (8 per lane) -> g_b*
            float lm[8], lw[8], ln[8];
            float amn = 3.0e38f, amx = -3.0e38f, ans = -3.0e38f;
            #pragma unroll
            for (int q = 0; q < 8; q++) {
                lm[q] = __uint_as_float(g_csmin[lane * 8 + q]);
                lw[q] = __uint_as_float(g_cwmax[lane * 8 + q]);
                ln[q] = __uint_as_float(g_cnsmin[lane * 8 + q]);
                amn = fminf(amn, lm[q]);
                amx = fmaxf(amx, lw[q]);
                ans = fmaxf(ans, ln[q]);
            }
            float smn = amn, smx = amx, sns = ans;
            #pragma unroll
            for (int off = 1; off < 32; off <<= 1) {
                float a = __shfl_down_sync(0xffffffffu, smn, off);
                float b = __shfl_down_sync(0xffffffffu, smx, off);
                float c2 = __shfl_down_sync(0xffffffffu, sns, off);
                if (lane + off < 32) {
                    smn = fminf(smn, a); smx = fmaxf(smx, b); sns = fmaxf(sns, c2);
                }
            }
            float tmn = __shfl_down_sync(0xffffffffu, smn, 1);
            float tmx = __shfl_down_sync(0xffffffffu, smx, 1);
            float tns = __shfl_down_sync(0xffffffffu, sns, 1);
            if (lane == 31) { tmn = 3.0e38f; tmx = -3.0e38f; tns = -3.0e38f; }
            float rmn = tmn, rmx = tmx, rns = tns;
            #pragma unroll
            for (int q = 7; q >= 0; q--) {
                rmn = fminf(rmn, lm[q]);
                rmx = fmaxf(rmx, lw[q]);
                rns = fmaxf(rns, ln[q]);
                g_bmin[lane * 8 + q] = rmn;
                g_bwub[lane * 8 + q] = rmx;
                g_bnsw[lane * 8 + q] = rns;
            }
            __threadfence();
            __syncwarp();
            if (lane == 0) atomicExch(&g_flag, 1);
        }
    }

    // --- Wait for bounds (deadlock-free: the 32 scatter CTAs are in wave 1)
    while (*(volatile int*)&g_flag == 0) __nanosleep(256);
    __threadfence();

    s_cmin[t] = g_bmin[t];
    s_cwub[t] = g_bwub[t];
    s_cnsw[t] = g_bnsw[t];
    __syncthreads();

    // --- Probe (proven R8 loop; REDUX replaces the 5-shuffle reduce)
    const int i = bid * 8 + warp;
    const float si = g_s[i];
    const int* __restrict__ arow = adj + (size_t)i * NN;

    float best = 0.0f;   // reference max always includes T[i,i] = 0
    int a = __ldg(&arow[g_idx[lane]]);

    for (int c = 0; c < NCHUNK; c++) {
        int na = 0;
        if (c + 1 < NCHUNK)
            na = __ldg(&arow[g_idx[(c + 1) * 32 + lane]]);   // 1-deep prefetch

        const int k = c * 32 + lane;
        float d = si - g_ss[k];
        float contrib = (d > 0.0f && a) ? d * g_ws[k] : 0.0f;
        unsigned wm = __reduce_max_sync(0xffffffffu, __float_as_uint(contrib));
        best = fmaxf(best, __uint_as_float(wm));   // contrib >= 0: bits monotone

        if (c + 1 < NCHUNK) {
            //  b1: (si - min s) * max w          (fp-monotone, exact-safe)
            //  b2: si*max(w) + max(-s*w) + slack (slack >> total rounding error)
            float b1 = (si - s_cmin[c + 1]) * s_cwub[c + 1];
            float b2 = si * s_cwub[c + 1] + s_cnsw[c + 1] + 1e-5f;
            if (fminf(b1, b2) <= best) break;
            a = na;
        }
    }

    if (lane == 0) {
        out[i * 3 + 0] = best;
        out[i * 3 + 1] = best;
        out[i * 3 + 2] = best;
    }
}

extern "C" void kernel_launch(void* const* d_in, const int* in_sizes, int n_in,
                              void* d_out, int out_size) {
    const float* x    = (const float*)d_in[0];
    const int*   adj  = (const int*)d_in[1];
    const float* Wphi = (const float*)d_in[2];
    // d_in[3] (W_theta) is unused in the forward pass.
    float* out = (float*)d_out;

    prep_kernel<<<GA, 128>>>(x, Wphi);
    probe_kernel<<<NN / 8, 256>>>(adj, out);
}

// round 17
// speedup vs baseline: 1.9343x; 1.9343x over previous
#include <cuda_runtime.h>
#include <cstdint>

#define NN 8192
#define KB 4096               // histogram buckets (fine sort -> tight bounds)
#define NCHUNK 256            // 256 chunks of 32 sorted candidates
#define SGRID 64              // scatter grid (64 * 128 = 8192)

// Scratch (device globals — no allocation allowed in kernel_launch).
// Zero-initialized at load; counters/hist self-reset each replay.
__device__ float    g_s[NN];          // s[j] by original index
__device__ float    g_wm[NN];         // wmax[j] by original index
__device__ int      g_bk[NN];         // bucket id by original index
__device__ __align__(16) int g_hist[KB];  // re-zeroed by scan_kernel each run
__device__ __align__(16) int g_cur[KB];   // exclusive offsets -> scatter cursors
__device__ float    g_ss[NN];         // s in bucket-sorted order
__device__ float    g_ws[NN];         // wmax in bucket-sorted order
__device__ int      g_idx[NN];        // original index in bucket-sorted order
__device__ unsigned g_csmin[NCHUNK];  // per-chunk min s   (float bits, atomicMin)
__device__ unsigned g_cwmax[NCHUNK];  // per-chunk max w   (float bits, atomicMax)
__device__ unsigned g_cnsmin[NCHUNK]; // per-chunk max -s*w (neg float bits, atomicMin)
__device__ float    g_bmin[NCHUNK];   // FINAL suffix min s
__device__ float    g_bwub[NCHUNK];   // FINAL suffix max w
__device__ float    g_bnsw[NCHUNK];   // FINAL suffix max -s*w
__device__ int      g_doneS;          // scatter completion counter (self-resets)

// K1: per-element s, wmax, bucket; histogram via spread global atomics
__global__ __launch_bounds__(128)
void bucket_kernel(const float* __restrict__ x, const float* __restrict__ Wphi) {
    int j = blockIdx.x * 128 + threadIdx.x;
    float s = x[3 * j + 0] + x[3 * j + 1] + x[3 * j + 2];
    float w0 = Wphi[j], w1 = Wphi[NN + j], w2 = Wphi[2 * NN + j];
    float w = fmaxf(w0, fmaxf(w1, w2));
    int b = (int)(s * (KB / 3.0f));
    b = max(0, min(KB - 1, b));
    g_s[j]  = s;
    g_wm[j] = w;
    g_bk[j] = b;
    atomicAdd(&g_hist[b], 1);
}

// K2: exclusive scan hist -> cur; zero hist for next replay; init chunk stats
__global__ __launch_bounds__(1024)
void scan_kernel() {
    __shared__ int warpsums[32];
    const int t = threadIdx.x, lane = t & 31, wid = t >> 5;

    int4 h = reinterpret_cast<const int4*>(g_hist)[t];           // buckets 4t..4t+3
    reinterpret_cast<int4*>(g_hist)[t] = make_int4(0, 0, 0, 0);  // ready for next run

    int lsum = h.x + h.y + h.z + h.w;
    int inc = lsum;
    #pragma unroll
    for (int off = 1; off < 32; off <<= 1) {
        int n = __shfl_up_sync(0xffffffffu, inc, off);
        if (lane >= off) inc += n;
    }
    if (lane == 31) warpsums[wid] = inc;
    __syncthreads();
    if (wid == 0) {
        int ws = warpsums[lane];
        int winc = ws;
        #pragma unroll
        for (int off = 1; off < 32; off <<= 1) {
            int n = __shfl_up_sync(0xffffffffu, winc, off);
            if (lane >= off) winc += n;
        }
        warpsums[lane] = winc - ws;   // exclusive warp offset
    }
    __syncthreads();
    int base = warpsums[wid] + (inc - lsum);
    int4 o;
    o.x = base;
    o.y = base + h.x;
    o.z = base + h.x + h.y;
    o.w = base + h.x + h.y + h.z;
    reinterpret_cast<int4*>(g_cur)[t] = o;

    if (t < NCHUNK) {
        g_csmin[t]  = 0x7F800000u;   // +inf
        g_cwmax[t]  = 0u;            // 0.0f (all w > 0)
        g_cnsmin[t] = 0xFFFFFFFFu;   // most-negative float bits
    }
}

// K3: scatter into sorted arrays + chunk stats via bitwise atomics; the
// LAST-finishing CTA computes the final suffix-bound arrays once.
__global__ __launch_bounds__(128)
void scatter_kernel() {
    const int t = threadIdx.x;
    int j = blockIdx.x * 128 + t;
    float s = g_s[j];
    float w = g_wm[j];
    int pos = atomicAdd(&g_cur[g_bk[j]], 1);
    g_ss[pos]  = s;
    g_ws[pos]  = w;
    g_idx[pos] = j;
    int c = pos >> 5;
    // s>0, w>0 -> int bits monotone; -s*w<=0 -> uint-min == float-max
    atomicMin(&g_csmin[c],  __float_as_uint(s));
    atomicMax(&g_cwmax[c],  __float_as_uint(w));
    atomicMin(&g_cnsmin[c], __float_as_uint(-s * w));

    // isLastBlockDone: release our atomics, then count
    __shared__ int isLast;
    __threadfence();
    __syncthreads();
    if (t == 0) isLast = (atomicAdd(&g_doneS, 1) == SGRID - 1);
    __syncthreads();
    if (!isLast) return;
    __threadfence();   // acquire: all CTAs' chunk-stat atomics now visible

    if (t < 32) {
        const int lane = t;
        // Single-warp suffix scan over 256 chunks (8 per lane) -> g_b*
        // (__ldcg: read through L2 where the atomics landed)
        float lm[8], lw[8], ln[8];
        float amn = 3.0e38f, amx = -3.0e38f, ans = -3.0e38f;
        #pragma unroll
        for (int q = 0; q < 8; q++) {
            lm[q] = __uint_as_float(__ldcg(&g_csmin[lane * 8 + q]));
            lw[q] = __uint_as_float(__ldcg(&g_cwmax[lane * 8 + q]));
            ln[q] = __uint_as_float(__ldcg(&g_cnsmin[lane * 8 + q]));
            amn = fminf(amn, lm[q]);
            amx = fmaxf(amx, lw[q]);
            ans = fmaxf(ans, ln[q]);
        }
        float smn = amn, smx = amx, sns = ans;
        #pragma unroll
        for (int off = 1; off < 32; off <<= 1) {
            float a = __shfl_down_sync(0xffffffffu, smn, off);
            float b = __shfl_down_sync(0xffffffffu, smx, off);
            float c2 = __shfl_down_sync(0xffffffffu, sns, off);
            if (lane + off < 32) {
                smn = fminf(smn, a); smx = fmaxf(smx, b); sns = fmaxf(sns, c2);
            }
        }
        float tmn = __shfl_down_sync(0xffffffffu, smn, 1);
        float tmx = __shfl_down_sync(0xffffffffu, smx, 1);
        float tns = __shfl_down_sync(0xffffffffu, sns, 1);
        if (lane == 31) { tmn = 3.0e38f; tmx = -3.0e38f; tns = -3.0e38f; }
        float rmn = tmn, rmx = tmx, rns = tns;
        #pragma unroll
        for (int q = 7; q >= 0; q--) {
            rmn = fminf(rmn, lm[q]);
            rmx = fmaxf(rmx, lw[q]);
            rns = fmaxf(rns, ln[q]);
            g_bmin[lane * 8 + q] = rmn;
            g_bwub[lane * 8 + q] = rmx;
            g_bnsw[lane * 8 + q] = rns;
        }
        if (lane == 0) g_doneS = 0;   // self-reset for next graph replay
    }
}

// K4: warp per row — R8's proven gate-every-chunk + 1-deep-prefetch loop.
// Light prologue (bounds precomputed); REDUX reduce; si-strided row map.
__global__ __launch_bounds__(256)
void probe_kernel(const int* __restrict__ adj, float* __restrict__ out) {
    __shared__ float s_cmin[NCHUNK], s_cwub[NCHUNK], s_cnsw[NCHUNK];

    const int t = threadIdx.x;
    const int lane = t & 31;
    const int warp = t >> 5;

    s_cmin[t] = g_bmin[t];
    s_cwub[t] = g_bwub[t];
    s_cnsw[t] = g_bnsw[t];
    __syncthreads();

    // Balanced mapping: warp w of CTA b takes sorted position w*1024 + b,
    // so each CTA holds one row from each si-octile (uniform CTA lifetimes).
    const int p = warp * (NN / 8) + blockIdx.x;
    const int i = g_idx[p];          // original row id (warp-uniform)
    const float si = g_ss[p];
    const int* __restrict__ arow = adj + (size_t)i * NN;

    float best = 0.0f;   // reference max always includes T[i,i] = 0
    int a = __ldg(&arow[g_idx[lane]]);

    for (int c = 0; c < NCHUNK; c++) {
        int na = 0;
        if (c + 1 < NCHUNK)
            na = __ldg(&arow[g_idx[(c + 1) * 32 + lane]]);   // 1-deep prefetch

        const int k = c * 32 + lane;
        float d = si - g_ss[k];
        float contrib = (d > 0.0f && a) ? d * g_ws[k] : 0.0f;
        // REDUX: exact max for nonnegative floats (bit order == value order)
        unsigned wm = __reduce_max_sync(0xffffffffu, __float_as_uint(contrib));
        best = fmaxf(best, __uint_as_float(wm));

        if (c + 1 < NCHUNK) {
            //  b1: (si - min s) * max w          (fp-monotone, exact-safe)
            //  b2: si*max(w) + max(-s*w) + slack (slack >> total rounding error)
            float b1 = (si - s_cmin[c + 1]) * s_cwub[c + 1];
            float b2 = si * s_cwub[c + 1] + s_cnsw[c + 1] + 1e-5f;
            if (fminf(b1, b2) <= best) break;
            a = na;
        }
    }

    if (lane == 0) {
        out[i * 3 + 0] = best;
        out[i * 3 + 1] = best;
        out[i * 3 + 2] = best;
    }
}

extern "C" void kernel_launch(void* const* d_in, const int* in_sizes, int n_in,
                              void* d_out, int out_size) {
    const float* x    = (const float*)d_in[0];
    const int*   adj  = (const int*)d_in[1];
    const float* Wphi = (const float*)d_in[2];
    // d_in[3] (W_theta) is unused in the forward pass.
    float* out = (float*)d_out;

    bucket_kernel<<<NN / 128, 128>>>(x, Wphi);
    scan_kernel<<<1, 1024>>>();
    scatter_kernel<<<SGRID, 128>>>();
    probe_kernel<<<NN / 8, 256>>>(adj, out);
}